// round 16
// baseline (speedup 1.0000x reference)
#include <cuda_runtime.h>
#include <cuda_fp16.h>
#include <cstdint>
#include <math.h>

// ---------------- problem constants ----------------
#define B_SZ      16384
#define KDIM      1024
#define OUT_DIM   1000
#define N_INT     1023
#define DEPTH     10
#define LAMBDA    1e-3f

// ---------------- scratch (device globals) ----------------
__device__ __half g_Xh[(size_t)B_SZ * KDIM];        // X as fp16
__device__ __half g_Ph[(size_t)B_SZ * KDIM];        // path probs fp16
__device__ __half g_Wh[(size_t)KDIM * KDIM];        // W_internal fp16
__device__ __half g_Lh[(size_t)KDIM * KDIM];        // W_leaf fp16
__device__ __half g_s[(size_t)B_SZ * KDIM];         // sigmoid-0.5, fp16 (centered)
__device__ float g_bias[KDIM];
__device__ float g_T[1023];
__device__ float g_U[2046];

// ---------------- PTX helpers (sm_80-class features only) ----------------
__device__ __forceinline__ uint32_t smem_u32(const void* p) {
    uint32_t a;
    asm("{ .reg .u64 t; cvta.to.shared.u64 t, %1; cvt.u32.u64 %0, t; }" : "=r"(a) : "l"(p));
    return a;
}

#define CP_ASYNC16(dst, src) \
    asm volatile("cp.async.cg.shared.global [%0], [%1], 16;" :: "r"(dst), "l"(src))
#define CP_COMMIT() asm volatile("cp.async.commit_group;" ::: "memory")
#define CP_WAIT(n)  asm volatile("cp.async.wait_group %0;" :: "n"(n) : "memory")

#define LDMX4(r0, r1, r2, r3, addr) \
    asm volatile("ldmatrix.sync.aligned.m8n8.x4.shared.b16 {%0,%1,%2,%3}, [%4];" \
        : "=r"(r0), "=r"(r1), "=r"(r2), "=r"(r3) : "r"(addr))

#define MMAF16(d, a, b) \
    asm volatile("mma.sync.aligned.m16n8k16.row.col.f32.f16.f16.f32 " \
        "{%0,%1,%2,%3}, {%4,%5,%6,%7}, {%8,%9}, {%0,%1,%2,%3};" \
        : "+f"((d)[0]), "+f"((d)[1]), "+f"((d)[2]), "+f"((d)[3]) \
        : "r"((a)[0]), "r"((a)[1]), "r"((a)[2]), "r"((a)[3]), \
          "r"((b)[0]), "r"((b)[1]))

// X: fp32 -> fp16
__global__ void conv_x_kernel(const float* __restrict__ src,
                              __half* __restrict__ dst) {
    size_t i = (size_t)blockIdx.x * blockDim.x + threadIdx.x;  // quad index
    float4 v = ((const float4*)src)[i];
    ((__half2*)dst)[2 * i]     = __floats2half2_rn(v.x, v.y);
    ((__half2*)dst)[2 * i + 1] = __floats2half2_rn(v.z, v.w);
}

// W_internal: repack [1023,1025] -> aligned fp16 + fp32 bias; zero T/U
__global__ void repack_w_kernel(const float* __restrict__ Wi,
                                __half* __restrict__ wh,
                                float* __restrict__ bias,
                                float* __restrict__ t, float* __restrict__ u) {
    int idx = blockIdx.x * blockDim.x + threadIdx.x;
    if (idx < KDIM * KDIM) {
        int n = idx >> 10, k = idx & 1023;
        float v = (n < N_INT) ? Wi[(size_t)n * 1025 + 1 + k] : 0.0f;
        wh[idx] = __float2half_rn(v);
    }
    if (idx < KDIM) bias[idx] = (idx < N_INT) ? Wi[(size_t)idx * 1025] : 0.0f;
    if (idx < 1023) t[idx] = 0.0f;
    if (idx < 2046) u[idx] = 0.0f;
}

__global__ void repack_l_kernel(const float* __restrict__ Wl,
                                __half* __restrict__ lh) {
    int idx = blockIdx.x * blockDim.x + threadIdx.x;
    if (idx < KDIM * KDIM) {
        int n = idx >> 10, k = idx & 1023;
        float v = (n < OUT_DIM) ? Wl[(size_t)n * KDIM + k] : 0.0f;
        lh[idx] = __float2half_rn(v);
    }
}

// ---------------- mma.sync GEMM: C[M,N] = A * B^T, pure fp16 ---------------
// CTA tile 128x128, BK=64, 2-stage cp.async ring, 256 threads (8 warps 4Mx2N,
// warp tile 32x64), 2 CTAs/SM. One __syncthreads per chunk; prefetch right
// after the barrier. SIG: sigmoid-0.5 -> fp16 centered. else fp32 out.
#define ROWB        144                   // 128B data + 16B pad (conflict-free)
#define TROWS       128
#define OFF_A       0
#define OFF_B       (TROWS * ROWB)        // 18432
#define STAGE_BYTES (2 * TROWS * ROWB)    // 36864
#define NSTAGE      2
#define NCHUNK      16                    // K=1024 / BK=64
#define DYN_SMEM    (NSTAGE * STAGE_BYTES + 512)

__device__ __forceinline__ void load_stage(
        const __half* __restrict__ A, const __half* __restrict__ B,
        int m0, int n0, int chunk, uint32_t sb, int tid) {
    const int r = tid >> 3;            // 0..31
    const int c = tid & 7;             // 16B eighth of the 128B row
    const int kk = chunk * 64 + c * 8; // fp16 element offset
    const uint32_t doff = (uint32_t)r * ROWB + (uint32_t)c * 16;
#pragma unroll
    for (int h = 0; h < 4; h++) {
        const int rr = r + h * 32;
        const uint32_t d = sb + doff + (uint32_t)(h * 32 * ROWB);
        CP_ASYNC16(d + OFF_A, A + (size_t)(m0 + rr) * KDIM + kk);
        CP_ASYNC16(d + OFF_B, B + (size_t)(n0 + rr) * KDIM + kk);
    }
}

template<bool SIG>
__global__ void __launch_bounds__(256, 2)
mma_gemm_kernel(const __half* __restrict__ A, const __half* __restrict__ B,
                const float* __restrict__ bias, void* __restrict__ Cv,
                int ldc, int nclip) {
    extern __shared__ char sm[];
    const uint32_t s0 = smem_u32(sm);
    float* bias_sh = (float*)(sm + NSTAGE * STAGE_BYTES);

    const int tid  = threadIdx.x;
    const int lane = tid & 31;
    const int wid  = tid >> 5;
    const int wm   = wid & 3;    // 4 M-warps of 32 rows
    const int wn   = wid >> 2;   // 2 N-warps of 64 cols
    const int m0   = blockIdx.y * 128;
    const int n0   = blockIdx.x * 128;

    if (SIG && tid < 128) bias_sh[tid] = bias[n0 + tid];

    float acc[2][8][4];
#pragma unroll
    for (int mi = 0; mi < 2; mi++)
#pragma unroll
        for (int ni = 0; ni < 8; ni++)
#pragma unroll
            for (int j = 0; j < 4; j++) acc[mi][ni][j] = 0.0f;

    const uint32_t a_off = (uint32_t)(wm * 32 + (lane & 15)) * ROWB
                         + (uint32_t)(lane >> 4) * 16;
    const uint32_t b_off = (uint32_t)(wn * 64 + ((lane >> 4) & 1) * 8 + (lane & 7)) * ROWB
                         + (uint32_t)((lane >> 3) & 1) * 16;

    load_stage(A, B, m0, n0, 0, s0, tid);
    CP_COMMIT();

    for (int s = 0; s < NCHUNK; s++) {
        CP_WAIT(0);
        __syncthreads();

        if (s + 1 < NCHUNK) {
            load_stage(A, B, m0, n0, s + 1,
                       s0 + (uint32_t)((s + 1) & 1) * STAGE_BYTES, tid);
            CP_COMMIT();
        }

        const uint32_t sb = s0 + (uint32_t)(s & 1) * STAGE_BYTES;

#pragma unroll
        for (int ks = 0; ks < 4; ks++) {
            uint32_t ar[2][4];
#pragma unroll
            for (int mi = 0; mi < 2; mi++) {
                const uint32_t ao = sb + a_off + (uint32_t)(mi * 16 * ROWB)
                                  + (uint32_t)(ks * 32);
                LDMX4(ar[mi][0], ar[mi][1], ar[mi][2], ar[mi][3], ao + OFF_A);
            }
#pragma unroll
            for (int half = 0; half < 2; half++) {
                uint32_t br[4][2];
#pragma unroll
                for (int p = 0; p < 2; p++) {
                    const int pj = half * 2 + p;
                    const uint32_t bo = sb + b_off + (uint32_t)(pj * 16 * ROWB)
                                      + (uint32_t)(ks * 32);
                    LDMX4(br[2 * p][0], br[2 * p][1], br[2 * p + 1][0], br[2 * p + 1][1],
                          bo + OFF_B);
                }
#pragma unroll
                for (int mi = 0; mi < 2; mi++)
#pragma unroll
                    for (int nj = 0; nj < 4; nj++)
                        MMAF16(acc[mi][half * 4 + nj], ar[mi], br[nj]);
            }
        }
    }

    // epilogue
    const int tr = lane >> 2;
    const int tc = (lane & 3) * 2;
#pragma unroll
    for (int mi = 0; mi < 2; mi++) {
#pragma unroll
        for (int ni = 0; ni < 8; ni++) {
            const int row = m0 + wm * 32 + mi * 16 + tr;
            const int col = n0 + wn * 64 + ni * 8 + tc;
            float v0 = acc[mi][ni][0], v1 = acc[mi][ni][1];
            float v2 = acc[mi][ni][2], v3 = acc[mi][ni][3];
            if (SIG) {
                const float b0 = bias_sh[col - n0];
                const float b1 = bias_sh[col - n0 + 1];
                v0 = 1.0f / (1.0f + __expf(-(v0 + b0))) - 0.5f;
                v1 = 1.0f / (1.0f + __expf(-(v1 + b1))) - 0.5f;
                v2 = 1.0f / (1.0f + __expf(-(v2 + b0))) - 0.5f;
                v3 = 1.0f / (1.0f + __expf(-(v3 + b1))) - 0.5f;
                __half* C = (__half*)Cv;
                *(__half2*)&C[(size_t)row * ldc + col]       = __floats2half2_rn(v0, v1);
                *(__half2*)&C[(size_t)(row + 8) * ldc + col] = __floats2half2_rn(v2, v3);
            } else {
                float* C = (float*)Cv;
                if (col < nclip) {
                    *(float2*)&C[(size_t)row * ldc + col]       = make_float2(v0, v1);
                    *(float2*)&C[(size_t)(row + 8) * ldc + col] = make_float2(v2, v3);
                }
            }
        }
    }
}

// ---------------- path: warp-per-sample, register-resident subtree --------
// Lane t owns the level-5 subtree covering leaves [32t, 32t+32). Levels 0-4
// are warp-cooperative via shuffles; levels 5-9 thread-local (unrolled).
// T/U partials in warp-private smem (deep levels transposed: kl*STRIDE + t
// for conflict-free accumulation); block epilogue reduces 4 copies and does
// one atomicAdd per entry.
#define PATH_WARPS  4
#define PATH_SPW    4      // samples per warp
#define PATH_WSTR   3072   // floats per warp-private region (1024 T + 2046 U)
#define PATH_SMEM   (PATH_WARPS * PATH_WSTR * 4)

__global__ void __launch_bounds__(128)
path_kernel(const __half* __restrict__ s_g,
            __half* __restrict__ ph,
            float* __restrict__ gT, float* __restrict__ gU) {
    extern __shared__ float acc[];     // [PATH_WARPS][PATH_WSTR]
    const int tid = threadIdx.x;
    const int w   = tid >> 5;
    const int t   = tid & 31;
    float* Tw = acc + w * PATH_WSTR;   // T partials at [0,1023)
    float* Uw = Tw + 1024;             // U partials at [0,2046)

    for (int i = tid; i < PATH_WARPS * PATH_WSTR; i += 128) acc[i] = 0.0f;
    __syncthreads();

    for (int it = 0; it < PATH_SPW; it++) {
        const int b = blockIdx.x * (PATH_WARPS * PATH_SPW) + w * PATH_SPW + it;
        const __half* srow = s_g + (size_t)b * 1024;

        // ---- shallow levels 0..4 (warp-cooperative) ----
        float np = 1.0f;                 // np_{d-1}[lane] (valid for lane < 2^d)
        int uo = 0;
#pragma unroll
        for (int d = 0; d < 5; d++) {
            const int nch = 2 << d;      // children at this level
            const int node = (1 << d) - 1 + (t >> 1);
            float sp = 0.5f + __half2float(__ldg(srow + node));
            float lp = (t & 1) ? (1.0f - sp) : sp;
            float np_par = __shfl_sync(0xffffffffu, np, t >> 1);
            float np_new = lp * np_par;                       // np_d[lane]
            float pn = __shfl_sync(0xffffffffu, np_new, t >> 1); // np_d[lane>>1]
            if (t < nch) Uw[uo + t] += lp * pn;
            if (t < (nch >> 1)) Tw[(1 << d) - 1 + t] += np_new;
            np = np_new;
            uo += nch;
        }

        // ---- deep levels 5..9 (thread-local subtree) ----
        float a[32];
        a[0] = np;                       // entry prob of level-5 node t
        int toffd = 31, uoffd = 62;
#pragma unroll
        for (int d = 5; d <= 9; d++) {
            const int C = 1 << (d - 5);  // local parent count
            float sn[16];
#pragma unroll
            for (int i = 0; i < C; i++)
                sn[i] = 0.5f + __half2float(
                    __ldg(srow + (1 << d) - 1 + t * C + i));
            // in-place expansion (descending i is clobber-safe)
#pragma unroll
            for (int i = C - 1; i >= 0; i--) {
                float c = a[i];
                float nk0 = c * sn[i];
                a[2 * i + 1] = c - nk0;
                a[2 * i]     = nk0;
            }
            // U: k = t*2C + kl ; np_d[k>>1] lives in lane t>>1's a[(t&1)*C + m]
#pragma unroll
            for (int m = 0; m < C; m++) {
                float lo = __shfl_sync(0xffffffffu, a[m],     t >> 1);
                float hi = __shfl_sync(0xffffffffu, a[C + m], t >> 1);
                float pn = (t & 1) ? hi : lo;
                float u0 = sn[m] * pn;
                Uw[uoffd + (2 * m) * 32 + t]     += u0;
                Uw[uoffd + (2 * m + 1) * 32 + t] += pn - u0;
            }
            // T: first 2^d children -> lanes 0..15 own all their children
            if (t < 16) {
#pragma unroll
                for (int kl = 0; kl < 2 * C; kl++)
                    Tw[toffd + kl * 16 + t] += a[kl];
            }
            toffd += (1 << d);
            uoffd += (2 << d);
        }

        // ---- leaf store: lane t owns leaves [32t, 32t+32) ----
        __half2* dst = (__half2*)(ph + (size_t)b * 1024 + 32 * t);
#pragma unroll
        for (int j = 0; j < 32; j += 2)
            dst[j >> 1] = __floats2half2_rn(a[j], a[j + 1]);
    }

    __syncthreads();
    // ---- reduce 4 warp copies -> global atomics ----
#pragma unroll
    for (int d = 0; d < DEPTH; d++) {
        const int n = 1 << d;
        const int toff = n - 1;
        for (int e = tid; e < n; e += 128) {
            int pos;
            if (d < 5) pos = toff + e;
            else {
                const int twoC = 1 << (d - 4);
                const int tt = e / twoC, kl = e % twoC;
                pos = toff + kl * 16 + tt;
            }
            float sum = acc[pos] + acc[PATH_WSTR + pos]
                      + acc[2 * PATH_WSTR + pos] + acc[3 * PATH_WSTR + pos];
            atomicAdd(&gT[toff + e], sum);
        }
    }
#pragma unroll
    for (int d = 0; d < DEPTH; d++) {
        const int n = 2 << d;
        const int uoff = n - 2;
        for (int e = tid; e < n; e += 128) {
            int pos;
            if (d < 5) pos = uoff + e;
            else {
                const int twoC = 1 << (d - 4);
                const int tt = e / twoC, kl = e % twoC;
                pos = uoff + kl * 32 + tt;
            }
            pos += 1024;
            float sum = acc[pos] + acc[PATH_WSTR + pos]
                      + acc[2 * PATH_WSTR + pos] + acc[3 * PATH_WSTR + pos];
            atomicAdd(&gU[uoff + e], sum);
        }
    }
}

// ---------------- regularizer scalar ----------------
__global__ void reg_kernel(const float* __restrict__ gT, const float* __restrict__ gU,
                           float* __restrict__ out) {
    float local = 0.0f;
    int toff = 0, uoff = 0;
#pragma unroll
    for (int d = 0; d < DEPTH; d++) {
        const int nout = 2 << d;
        const float factor = LAMBDA * exp2f(-(float)d);
        for (int k = threadIdx.x; k < nout; k += 256) {
            float den = gT[toff + (k >> 1)] + 1e-8f;
            float alpha = gU[uoff + k] / den;
            local += factor * (-0.5f) * (logf(alpha) + logf(1.0f - alpha));
        }
        toff += (1 << d);
        uoff += nout;
    }
    __shared__ float red[256];
    red[threadIdx.x] = local;
    __syncthreads();
    for (int s = 128; s > 0; s >>= 1) {
        if (threadIdx.x < s) red[threadIdx.x] += red[threadIdx.x + s];
        __syncthreads();
    }
    if (threadIdx.x == 0) out[0] = red[0];
}

// ---------------- launch ----------------
extern "C" void kernel_launch(void* const* d_in, const int* in_sizes, int n_in,
                              void* d_out, int out_size) {
    const float* X  = (const float*)d_in[0];   // [16384, 1024]
    const float* Wi = (const float*)d_in[1];   // [1023, 1025]
    const float* Wl = (const float*)d_in[2];   // [1000, 1024]
    float* out = (float*)d_out;

    __half *xh, *php, *wh, *lh, *s_p;
    float *bias_p, *t_p, *u_p;
    cudaGetSymbolAddress((void**)&xh,   g_Xh);
    cudaGetSymbolAddress((void**)&php,  g_Ph);
    cudaGetSymbolAddress((void**)&wh,   g_Wh);
    cudaGetSymbolAddress((void**)&lh,   g_Lh);
    cudaGetSymbolAddress((void**)&s_p,  g_s);
    cudaGetSymbolAddress((void**)&bias_p, g_bias);
    cudaGetSymbolAddress((void**)&t_p,  g_T);
    cudaGetSymbolAddress((void**)&u_p,  g_U);

    cudaFuncSetAttribute(mma_gemm_kernel<true>,
                         cudaFuncAttributeMaxDynamicSharedMemorySize, DYN_SMEM);
    cudaFuncSetAttribute(mma_gemm_kernel<false>,
                         cudaFuncAttributeMaxDynamicSharedMemorySize, DYN_SMEM);
    cudaFuncSetAttribute(path_kernel,
                         cudaFuncAttributeMaxDynamicSharedMemorySize, PATH_SMEM);

    // 1. convert X and weights to fp16
    conv_x_kernel<<<(B_SZ * KDIM / 4 + 255) / 256, 256>>>(X, xh);
    repack_w_kernel<<<(KDIM * KDIM + 255) / 256, 256>>>(Wi, wh, bias_p, t_p, u_p);
    repack_l_kernel<<<(KDIM * KDIM + 255) / 256, 256>>>(Wl, lh);

    // 2. GEMM1 + bias + sigmoid-0.5 -> g_s (fp16 centered, ld=1024)
    {
        dim3 grid(8, B_SZ / 128);   // (8, 128)
        mma_gemm_kernel<true><<<grid, 256, DYN_SMEM>>>(
            xh, wh, bias_p, s_p, 1024, 1024);
    }

    // 3. path probs (fp16) + regularizer partial sums
    {
        int grid = B_SZ / (PATH_WARPS * PATH_SPW);   // 1024
        path_kernel<<<grid, 128, PATH_SMEM>>>(s_p, php, t_p, u_p);
    }

    // 4. GEMM2: predictions = path @ W_leaf^T -> d_out (fp32, ld=1000)
    {
        dim3 grid(8, B_SZ / 128);
        mma_gemm_kernel<false><<<grid, 256, DYN_SMEM>>>(
            php, lh, nullptr, out, OUT_DIM, OUT_DIM);
    }

    // 5. regularizer scalar -> last output element
    reg_kernel<<<1, 256>>>(t_p, u_p, out + (out_size - 1));
}

// round 17
// speedup vs baseline: 1.2231x; 1.2231x over previous
#include <cuda_runtime.h>
#include <cuda_fp16.h>
#include <cstdint>
#include <math.h>

// ---------------- problem constants ----------------
#define B_SZ      16384
#define KDIM      1024
#define OUT_DIM   1000
#define N_INT     1023
#define DEPTH     10
#define LAMBDA    1e-3f

// ---------------- scratch (device globals) ----------------
__device__ __half g_Xh[(size_t)B_SZ * KDIM];        // X as fp16
__device__ __half g_Ph[(size_t)B_SZ * KDIM];        // path probs fp16
__device__ __half g_Wh[(size_t)KDIM * KDIM];        // W_internal fp16
__device__ __half g_Lh[(size_t)KDIM * KDIM];        // W_leaf fp16
__device__ __half g_s[(size_t)B_SZ * KDIM];         // sigmoid-0.5, fp16 (centered)
__device__ float g_bias[KDIM];
__device__ float g_T[1023];
__device__ float g_U[2046];

// ---------------- PTX helpers (sm_80-class features only) ----------------
__device__ __forceinline__ uint32_t smem_u32(const void* p) {
    uint32_t a;
    asm("{ .reg .u64 t; cvta.to.shared.u64 t, %1; cvt.u32.u64 %0, t; }" : "=r"(a) : "l"(p));
    return a;
}

#define CP_ASYNC16(dst, src) \
    asm volatile("cp.async.cg.shared.global [%0], [%1], 16;" :: "r"(dst), "l"(src))
#define CP_COMMIT() asm volatile("cp.async.commit_group;" ::: "memory")
#define CP_WAIT(n)  asm volatile("cp.async.wait_group %0;" :: "n"(n) : "memory")

#define LDMX4(r0, r1, r2, r3, addr) \
    asm volatile("ldmatrix.sync.aligned.m8n8.x4.shared.b16 {%0,%1,%2,%3}, [%4];" \
        : "=r"(r0), "=r"(r1), "=r"(r2), "=r"(r3) : "r"(addr))

#define MMAF16(d, a, b) \
    asm volatile("mma.sync.aligned.m16n8k16.row.col.f32.f16.f16.f32 " \
        "{%0,%1,%2,%3}, {%4,%5,%6,%7}, {%8,%9}, {%0,%1,%2,%3};" \
        : "+f"((d)[0]), "+f"((d)[1]), "+f"((d)[2]), "+f"((d)[3]) \
        : "r"((a)[0]), "r"((a)[1]), "r"((a)[2]), "r"((a)[3]), \
          "r"((b)[0]), "r"((b)[1]))

// ---------------- fused prep: conv X + repack W/L + zero T/U --------------
// blockIdx.x in [0, 16384): X fp32->fp16 (256 float4 quads per block)
// blockIdx.x in [16384, 20480): W_internal repack + bias + T/U zero
// blockIdx.x in [20480, 24576): W_leaf repack
#define PREP_XBLKS 16384
#define PREP_WBLKS 4096
#define PREP_TOTAL (PREP_XBLKS + 2 * PREP_WBLKS)

__global__ void prep_kernel(const float* __restrict__ X,
                            const float* __restrict__ Wi,
                            const float* __restrict__ Wl,
                            __half* __restrict__ xh,
                            __half* __restrict__ wh,
                            __half* __restrict__ lh,
                            float* __restrict__ bias,
                            float* __restrict__ t, float* __restrict__ u) {
    const int bx = blockIdx.x;
    if (bx < PREP_XBLKS) {
        size_t i = (size_t)bx * 256 + threadIdx.x;   // quad index
        float4 v = ((const float4*)X)[i];
        ((__half2*)xh)[2 * i]     = __floats2half2_rn(v.x, v.y);
        ((__half2*)xh)[2 * i + 1] = __floats2half2_rn(v.z, v.w);
    } else if (bx < PREP_XBLKS + PREP_WBLKS) {
        int idx = (bx - PREP_XBLKS) * 256 + threadIdx.x;
        int n = idx >> 10, k = idx & 1023;
        float v = (n < N_INT) ? Wi[(size_t)n * 1025 + 1 + k] : 0.0f;
        wh[idx] = __float2half_rn(v);
        if (idx < KDIM) bias[idx] = (idx < N_INT) ? Wi[(size_t)idx * 1025] : 0.0f;
        if (idx < 1023) t[idx] = 0.0f;
        if (idx < 2046) u[idx] = 0.0f;
    } else {
        int idx = (bx - PREP_XBLKS - PREP_WBLKS) * 256 + threadIdx.x;
        int n = idx >> 10, k = idx & 1023;
        float v = (n < OUT_DIM) ? Wl[(size_t)n * KDIM + k] : 0.0f;
        lh[idx] = __float2half_rn(v);
    }
}

// ---------------- mma.sync GEMM: C[M,N] = A * B^T, pure fp16 ---------------
// CTA tile 128x128, BK=64, 2-stage cp.async ring, 256 threads (8 warps 4Mx2N,
// warp tile 32x64), 2 CTAs/SM. One __syncthreads per chunk; prefetch right
// after the barrier. SIG: sigmoid-0.5 -> fp16 centered. else fp32 out.
#define ROWB        144                   // 128B data + 16B pad (conflict-free)
#define TROWS       128
#define OFF_A       0
#define OFF_B       (TROWS * ROWB)        // 18432
#define STAGE_BYTES (2 * TROWS * ROWB)    // 36864
#define NSTAGE      2
#define NCHUNK      16                    // K=1024 / BK=64
#define DYN_SMEM    (NSTAGE * STAGE_BYTES + 512)

__device__ __forceinline__ void load_stage(
        const __half* __restrict__ A, const __half* __restrict__ B,
        int m0, int n0, int chunk, uint32_t sb, int tid) {
    const int r = tid >> 3;            // 0..31
    const int c = tid & 7;             // 16B eighth of the 128B row
    const int kk = chunk * 64 + c * 8; // fp16 element offset
    const uint32_t doff = (uint32_t)r * ROWB + (uint32_t)c * 16;
#pragma unroll
    for (int h = 0; h < 4; h++) {
        const int rr = r + h * 32;
        const uint32_t d = sb + doff + (uint32_t)(h * 32 * ROWB);
        CP_ASYNC16(d + OFF_A, A + (size_t)(m0 + rr) * KDIM + kk);
        CP_ASYNC16(d + OFF_B, B + (size_t)(n0 + rr) * KDIM + kk);
    }
}

template<bool SIG>
__global__ void __launch_bounds__(256, 2)
mma_gemm_kernel(const __half* __restrict__ A, const __half* __restrict__ B,
                const float* __restrict__ bias, void* __restrict__ Cv,
                int ldc, int nclip) {
    extern __shared__ char sm[];
    const uint32_t s0 = smem_u32(sm);
    float* bias_sh = (float*)(sm + NSTAGE * STAGE_BYTES);

    const int tid  = threadIdx.x;
    const int lane = tid & 31;
    const int wid  = tid >> 5;
    const int wm   = wid & 3;    // 4 M-warps of 32 rows
    const int wn   = wid >> 2;   // 2 N-warps of 64 cols
    const int m0   = blockIdx.y * 128;
    const int n0   = blockIdx.x * 128;

    if (SIG && tid < 128) bias_sh[tid] = bias[n0 + tid];

    float acc[2][8][4];
#pragma unroll
    for (int mi = 0; mi < 2; mi++)
#pragma unroll
        for (int ni = 0; ni < 8; ni++)
#pragma unroll
            for (int j = 0; j < 4; j++) acc[mi][ni][j] = 0.0f;

    const uint32_t a_off = (uint32_t)(wm * 32 + (lane & 15)) * ROWB
                         + (uint32_t)(lane >> 4) * 16;
    const uint32_t b_off = (uint32_t)(wn * 64 + ((lane >> 4) & 1) * 8 + (lane & 7)) * ROWB
                         + (uint32_t)((lane >> 3) & 1) * 16;

    load_stage(A, B, m0, n0, 0, s0, tid);
    CP_COMMIT();

    for (int s = 0; s < NCHUNK; s++) {
        CP_WAIT(0);
        __syncthreads();

        if (s + 1 < NCHUNK) {
            load_stage(A, B, m0, n0, s + 1,
                       s0 + (uint32_t)((s + 1) & 1) * STAGE_BYTES, tid);
            CP_COMMIT();
        }

        const uint32_t sb = s0 + (uint32_t)(s & 1) * STAGE_BYTES;

#pragma unroll
        for (int ks = 0; ks < 4; ks++) {
            uint32_t ar[2][4];
#pragma unroll
            for (int mi = 0; mi < 2; mi++) {
                const uint32_t ao = sb + a_off + (uint32_t)(mi * 16 * ROWB)
                                  + (uint32_t)(ks * 32);
                LDMX4(ar[mi][0], ar[mi][1], ar[mi][2], ar[mi][3], ao + OFF_A);
            }
#pragma unroll
            for (int half = 0; half < 2; half++) {
                uint32_t br[4][2];
#pragma unroll
                for (int p = 0; p < 2; p++) {
                    const int pj = half * 2 + p;
                    const uint32_t bo = sb + b_off + (uint32_t)(pj * 16 * ROWB)
                                      + (uint32_t)(ks * 32);
                    LDMX4(br[2 * p][0], br[2 * p][1], br[2 * p + 1][0], br[2 * p + 1][1],
                          bo + OFF_B);
                }
#pragma unroll
                for (int mi = 0; mi < 2; mi++)
#pragma unroll
                    for (int nj = 0; nj < 4; nj++)
                        MMAF16(acc[mi][half * 4 + nj], ar[mi], br[nj]);
            }
        }
    }

    // epilogue
    const int tr = lane >> 2;
    const int tc = (lane & 3) * 2;
#pragma unroll
    for (int mi = 0; mi < 2; mi++) {
#pragma unroll
        for (int ni = 0; ni < 8; ni++) {
            const int row = m0 + wm * 32 + mi * 16 + tr;
            const int col = n0 + wn * 64 + ni * 8 + tc;
            float v0 = acc[mi][ni][0], v1 = acc[mi][ni][1];
            float v2 = acc[mi][ni][2], v3 = acc[mi][ni][3];
            if (SIG) {
                const float b0 = bias_sh[col - n0];
                const float b1 = bias_sh[col - n0 + 1];
                v0 = 1.0f / (1.0f + __expf(-(v0 + b0))) - 0.5f;
                v1 = 1.0f / (1.0f + __expf(-(v1 + b1))) - 0.5f;
                v2 = 1.0f / (1.0f + __expf(-(v2 + b0))) - 0.5f;
                v3 = 1.0f / (1.0f + __expf(-(v3 + b1))) - 0.5f;
                __half* C = (__half*)Cv;
                *(__half2*)&C[(size_t)row * ldc + col]       = __floats2half2_rn(v0, v1);
                *(__half2*)&C[(size_t)(row + 8) * ldc + col] = __floats2half2_rn(v2, v3);
            } else {
                float* C = (float*)Cv;
                if (col < nclip) {
                    *(float2*)&C[(size_t)row * ldc + col]       = make_float2(v0, v1);
                    *(float2*)&C[(size_t)(row + 8) * ldc + col] = make_float2(v2, v3);
                }
            }
        }
    }
}

// ---------------- path + regularizer partial sums (R14-proven) ------------
// Pair-based processing; two samples interleaved per barrier phase.
#define SAMPLES_PER_BLOCK 8

__global__ void __launch_bounds__(256)
path_kernel(const __half* __restrict__ s_g,
            __half* __restrict__ ph,
            float* __restrict__ gT, float* __restrict__ gU) {
    __shared__ float s_sh[2][1024];
    __shared__ float bufA[2][1024];
    __shared__ float bufB[2][1024];
    __shared__ float Tacc[1023];
    __shared__ float Uacc[2046];

    const int tid = threadIdx.x;
    for (int i = tid; i < 1023; i += 256) Tacc[i] = 0.0f;
    for (int i = tid; i < 2046; i += 256) Uacc[i] = 0.0f;

    const int base = blockIdx.x * SAMPLES_PER_BLOCK;

    for (int s = 0; s < SAMPLES_PER_BLOCK; s += 2) {
        const int b0 = base + s;
        __syncthreads();
        for (int i = tid; i < 1024; i += 256) {
            const int smp = i >> 9;
            const int j   = i & 511;
            __half2 cv = ((const __half2*)(s_g + (size_t)(b0 + smp) * 1024))[j];
            float2 cf = __half22float2(cv);
            s_sh[smp][2 * j]     = 0.5f + cf.x;
            s_sh[smp][2 * j + 1] = 0.5f + cf.y;
        }
        if (tid < 2) bufA[tid][0] = 1.0f;
        __syncthreads();

        float* cur0 = bufA[0]; float* nxt0 = bufB[0];
        float* cur1 = bufA[1]; float* nxt1 = bufB[1];
        int toff = 0, uoff = 0;

#pragma unroll
        for (int d = 0; d < DEPTH; d++) {
            const int npair = 1 << d;
            const int nbase = npair - 1;
#pragma unroll 1
            for (int j = tid; j < npair; j += 256) {
                {
                    float sv = s_sh[0][nbase + j];
                    float cj = cur0[j];
                    float nk0 = cj * sv;
                    float nk1 = cj - nk0;
                    nxt0[2 * j]     = nk0;
                    nxt0[2 * j + 1] = nk1;
                    float svp = s_sh[0][nbase + (j >> 1)];
                    float lpp = (j & 1) ? (1.0f - svp) : svp;
                    float pn  = cur0[j >> 1] * lpp;
                    float u0  = sv * pn;
                    Uacc[uoff + 2 * j]     += u0;
                    Uacc[uoff + 2 * j + 1] += pn - u0;
                    if (2 * j < npair)     Tacc[toff + 2 * j]     += nk0;
                    if (2 * j + 1 < npair) Tacc[toff + 2 * j + 1] += nk1;
                }
                {
                    float sv = s_sh[1][nbase + j];
                    float cj = cur1[j];
                    float nk0 = cj * sv;
                    float nk1 = cj - nk0;
                    nxt1[2 * j]     = nk0;
                    nxt1[2 * j + 1] = nk1;
                    float svp = s_sh[1][nbase + (j >> 1)];
                    float lpp = (j & 1) ? (1.0f - svp) : svp;
                    float pn  = cur1[j >> 1] * lpp;
                    float u0  = sv * pn;
                    Uacc[uoff + 2 * j]     += u0;
                    Uacc[uoff + 2 * j + 1] += pn - u0;
                    if (2 * j < npair)     Tacc[toff + 2 * j]     += nk0;
                    if (2 * j + 1 < npair) Tacc[toff + 2 * j + 1] += nk1;
                }
            }
            __syncthreads();
            toff += npair;
            uoff += 2 * npair;
            float* t;
            t = cur0; cur0 = nxt0; nxt0 = t;
            t = cur1; cur1 = nxt1; nxt1 = t;
        }

        for (int l = tid; l < 1024; l += 256) {
            ph[(size_t)b0 * 1024 + l]       = __float2half_rn(cur0[l]);
            ph[(size_t)(b0 + 1) * 1024 + l] = __float2half_rn(cur1[l]);
        }
    }

    __syncthreads();
    for (int i = tid; i < 1023; i += 256) atomicAdd(&gT[i], Tacc[i]);
    for (int i = tid; i < 2046; i += 256) atomicAdd(&gU[i], Uacc[i]);
}

// ---------------- regularizer scalar ----------------
__global__ void reg_kernel(const float* __restrict__ gT, const float* __restrict__ gU,
                           float* __restrict__ out) {
    float local = 0.0f;
    int toff = 0, uoff = 0;
#pragma unroll
    for (int d = 0; d < DEPTH; d++) {
        const int nout = 2 << d;
        const float factor = LAMBDA * exp2f(-(float)d);
        for (int k = threadIdx.x; k < nout; k += 256) {
            float den = gT[toff + (k >> 1)] + 1e-8f;
            float alpha = gU[uoff + k] / den;
            local += factor * (-0.5f) * (logf(alpha) + logf(1.0f - alpha));
        }
        toff += (1 << d);
        uoff += nout;
    }
    __shared__ float red[256];
    red[threadIdx.x] = local;
    __syncthreads();
    for (int s = 128; s > 0; s >>= 1) {
        if (threadIdx.x < s) red[threadIdx.x] += red[threadIdx.x + s];
        __syncthreads();
    }
    if (threadIdx.x == 0) out[0] = red[0];
}

// ---------------- launch ----------------
extern "C" void kernel_launch(void* const* d_in, const int* in_sizes, int n_in,
                              void* d_out, int out_size) {
    const float* X  = (const float*)d_in[0];   // [16384, 1024]
    const float* Wi = (const float*)d_in[1];   // [1023, 1025]
    const float* Wl = (const float*)d_in[2];   // [1000, 1024]
    float* out = (float*)d_out;

    __half *xh, *php, *wh, *lh, *s_p;
    float *bias_p, *t_p, *u_p;
    cudaGetSymbolAddress((void**)&xh,   g_Xh);
    cudaGetSymbolAddress((void**)&php,  g_Ph);
    cudaGetSymbolAddress((void**)&wh,   g_Wh);
    cudaGetSymbolAddress((void**)&lh,   g_Lh);
    cudaGetSymbolAddress((void**)&s_p,  g_s);
    cudaGetSymbolAddress((void**)&bias_p, g_bias);
    cudaGetSymbolAddress((void**)&t_p,  g_T);
    cudaGetSymbolAddress((void**)&u_p,  g_U);

    cudaFuncSetAttribute(mma_gemm_kernel<true>,
                         cudaFuncAttributeMaxDynamicSharedMemorySize, DYN_SMEM);
    cudaFuncSetAttribute(mma_gemm_kernel<false>,
                         cudaFuncAttributeMaxDynamicSharedMemorySize, DYN_SMEM);

    // 1. fused prep: X->fp16, W/L repack, bias, T/U zero (one launch)
    prep_kernel<<<PREP_TOTAL, 256>>>(X, Wi, Wl, xh, wh, lh, bias_p, t_p, u_p);

    // 2. GEMM1 + bias + sigmoid-0.5 -> g_s (fp16 centered, ld=1024)
    {
        dim3 grid(8, B_SZ / 128);   // (8, 128)
        mma_gemm_kernel<true><<<grid, 256, DYN_SMEM>>>(
            xh, wh, bias_p, s_p, 1024, 1024);
    }

    // 3. path probs (fp16) + regularizer partial sums
    path_kernel<<<B_SZ / SAMPLES_PER_BLOCK, 256>>>(s_p, php, t_p, u_p);

    // 4. GEMM2: predictions = path @ W_leaf^T -> d_out (fp32, ld=1000)
    {
        dim3 grid(8, B_SZ / 128);
        mma_gemm_kernel<false><<<grid, 256, DYN_SMEM>>>(
            php, lh, nullptr, out, OUT_DIM, OUT_DIM);
    }

    // 5. regularizer scalar -> last output element
    reg_kernel<<<1, 256>>>(t_p, u_p, out + (out_size - 1));
}